// round 17
// baseline (speedup 1.0000x reference)
#include <cuda_runtime.h>
#include <cuda_fp16.h>
#include <math.h>
#include <stdint.h>

#define KDIM 1024
#define NH   4096
#define NTOT 8192
#define BM   128
#define NTILES (NTOT / BM)                       // 64
#define NBLOCKS (NTILES * (NTILES + 1) / 2)      // 2080
#define CHUNK 64                                 // K elements per stage (128 bytes)
#define NCHUNK (KDIM / CHUNK)                    // 16
#define NST 2
#define TILE_BYTES (BM * 128)                    // 16 KB
#define STAGE_BYTES (2 * TILE_BYTES)             // 32 KB
#define DYN_BYTES (NST * STAGE_BYTES + 256)      // ~64.25 KB

#define NCVT 256                                 // converter CTAs (32 rows each)

// ---------------- device scratch (zero-initialized at load; self-resetting) ----------------
__device__ float  g_sq[NTOT];
__device__ float  g_colsum[KDIM];
__device__ double g_sumsq;
__device__ float  g_coef;                    // -log2(e) / (16 * bandwidth)
__device__ unsigned g_coef_ready;
__device__ double g_accum;
__device__ unsigned g_donectr;
__device__ unsigned g_cvt_cnt[NTILES];       // per-128-row-block sub-slice counters (4 = ready)
__device__ unsigned g_cvt_total;
__device__ __half g_total[(size_t)NTOT * KDIM];  // f16 copy of [S;T]

// ---------------- PTX helpers (plain sm_80+ PTX) ----------------
__device__ __forceinline__ uint32_t smem_u32(const void* p) {
  uint32_t a;
  asm("{ .reg .u64 t; cvta.to.shared.u64 t, %1; cvt.u32.u64 %0, t; }" : "=r"(a) : "l"(p));
  return a;
}
__device__ __forceinline__ void cp16(uint32_t dst, const void* src) {
  asm volatile("cp.async.cg.shared.global [%0], [%1], 16;" :: "r"(dst), "l"(src) : "memory");
}
__device__ __forceinline__ void cp_commit() {
  asm volatile("cp.async.commit_group;" ::: "memory");
}
template <int N>
__device__ __forceinline__ void cp_wait() {
  asm volatile("cp.async.wait_group %0;" :: "n"(N) : "memory");
}
__device__ __forceinline__ void ldsm4(uint32_t* r, uint32_t addr) {
  asm volatile("ldmatrix.sync.aligned.m8n8.x4.shared.b16 {%0,%1,%2,%3}, [%4];"
               : "=r"(r[0]), "=r"(r[1]), "=r"(r[2]), "=r"(r[3]) : "r"(addr));
}
// f16 x f16 -> f16 accumulate (2 c-regs = 4 packed halves)
__device__ __forceinline__ void mma16816h(uint32_t* c, const uint32_t* a,
                                          uint32_t b0, uint32_t b1) {
  asm volatile(
    "mma.sync.aligned.m16n8k16.row.col.f16.f16.f16.f16 "
    "{%0,%1}, {%2,%3,%4,%5}, {%6,%7}, {%0,%1};"
    : "+r"(c[0]), "+r"(c[1])
    : "r"(a[0]), "r"(a[1]), "r"(a[2]), "r"(a[3]), "r"(b0), "r"(b1));
}

// ---------------- single fused kernel ----------------
// SW128 swizzle on 128-byte rows: 16B-chunk index (bits [6:4]) XOR (row & 7).
__device__ __forceinline__ void load_stage(uint32_t sA, const __half* Ab,
                                           const __half* Bb, int t, int tid) {
  #pragma unroll
  for (int i = 0; i < 4; ++i) {
    int g   = tid + i * 256;
    int row = g >> 3;
    int cc  = g & 7;
    uint32_t soff = (uint32_t)row * 128u + (uint32_t)((cc ^ (row & 7)) << 4);
    const char* ga = (const char*)(Ab + (size_t)row * KDIM + t * CHUNK) + cc * 16;
    const char* gb = (const char*)(Bb + (size_t)row * KDIM + t * CHUNK) + cc * 16;
    cp16(sA + soff, ga);
    cp16(sA + TILE_BYTES + soff, gb);
  }
  cp_commit();
}

__global__ void __launch_bounds__(256, 3)
k_gemm(const float* __restrict__ S, const float* __restrict__ T,
       float* __restrict__ out) {
  extern __shared__ char dsm[];
  __shared__ double s_red[8];
  __shared__ double s_cred[256];
  __shared__ unsigned s_last;

  const int tid  = threadIdx.x;
  const int wid  = tid >> 5;
  const int lane = tid & 31;
  const int bid  = blockIdx.x;

  // ================= phase 0: conversion (CTAs 0..255) =================
  if (bid < NCVT) {
    float* scol = (float*)dsm;          // 1024 floats, reused before tile loads
    __shared__ double ssq[8];

    #pragma unroll
    for (int i = 0; i < KDIM / 256; ++i) scol[tid + i * 256] = 0.f;
    __syncthreads();

    float4 colacc[8];
    #pragma unroll
    for (int i = 0; i < 8; ++i) colacc[i] = make_float4(0.f, 0.f, 0.f, 0.f);

    double wsumsq = 0.0;   // lane 0 accumulates full row norms

    #pragma unroll
    for (int r = 0; r < 4; ++r) {
      int row = bid * 32 + wid * 4 + r;
      const float4* src = (const float4*)((row < NH) ? (S + (size_t)row * KDIM)
                                                     : (T + (size_t)(row - NH) * KDIM));
      float sq = 0.f;
      #pragma unroll
      for (int i = 0; i < 8; ++i) {
        float4 v = src[i * 32 + lane];
        sq += v.x * v.x + v.y * v.y + v.z * v.z + v.w * v.w;
        colacc[i].x += v.x; colacc[i].y += v.y;
        colacc[i].z += v.z; colacc[i].w += v.w;
        __half2 lo = __floats2half2_rn(v.x, v.y);
        __half2 hi = __floats2half2_rn(v.z, v.w);
        uint2 pk;
        pk.x = *(uint32_t*)&lo;
        pk.y = *(uint32_t*)&hi;
        *(uint2*)(g_total + (size_t)row * KDIM + i * 128 + lane * 4) = pk;
      }
      #pragma unroll
      for (int o = 16; o; o >>= 1) sq += __shfl_xor_sync(0xffffffffu, sq, o);
      if (lane == 0) g_sq[row] = sq;
      wsumsq += (double)sq;
    }

    #pragma unroll
    for (int i = 0; i < 8; ++i) {
      int c = i * 128 + lane * 4;
      atomicAdd(&scol[c + 0], colacc[i].x);
      atomicAdd(&scol[c + 1], colacc[i].y);
      atomicAdd(&scol[c + 2], colacc[i].z);
      atomicAdd(&scol[c + 3], colacc[i].w);
    }
    if (lane == 0) ssq[wid] = wsumsq;
    __syncthreads();

    #pragma unroll
    for (int i = 0; i < KDIM / 256; ++i) {
      int c = tid + i * 256;
      atomicAdd(&g_colsum[c], scol[c]);
    }
    if (tid == 0) {
      double t = 0.0;
      #pragma unroll
      for (int i = 0; i < 8; ++i) t += ssq[i];
      atomicAdd(&g_sumsq, t);
    }

    // publish this slice
    __threadfence();
    __syncthreads();
    if (tid == 0) {
      atomicAdd(&g_cvt_cnt[bid >> 2], 1u);
      s_last = atomicAdd(&g_cvt_total, 1u);
    }
    __syncthreads();

    // the 256th finisher's block computes the bandwidth coefficient
    if (s_last == NCVT - 1) {
      __threadfence();
      float4 v = *(const float4*)&g_colsum[tid * 4];
      s_cred[tid] = (double)v.x * v.x + (double)v.y * v.y
                  + (double)v.z * v.z + (double)v.w * v.w;
      *(float4*)&g_colsum[tid * 4] = make_float4(0.f, 0.f, 0.f, 0.f);  // reset
      __syncthreads();
      for (int s = 128; s; s >>= 1) {
        if (tid < s) s_cred[tid] += s_cred[tid + s];
        __syncthreads();
      }
      if (tid == 0) {
        double colsq = s_cred[0];
        double sumsq = g_sumsq;
        g_sumsq = 0.0;   // reset for next replay
        double sumL2 = 2.0 * (double)NTOT * sumsq - 2.0 * colsq;
        double bw = sumL2 / ((double)NTOT * (double)NTOT - (double)NTOT);
        bw *= 0.25;
        g_coef = (float)(-1.4426950408889634 / (16.0 * bw));   // log2(e) folded
        __threadfence();
        atomicExch(&g_coef_ready, 1u);
      }
    }
    __syncthreads();   // dsm (scol) free for tile stages
  }

  // ================= phase 1: Gram tile =================
  // triangular tile decode: bid = bp*(bp+1)/2 + bq
  int bp = (int)((sqrtf(8.0f * (float)bid + 1.0f) - 1.0f) * 0.5f);
  while ((bp + 1) * (bp + 2) / 2 <= bid) ++bp;
  while (bp * (bp + 1) / 2 > bid) --bp;
  int bq = bid - bp * (bp + 1) / 2;
  const int rowBase = bp * BM;
  const int colBase = bq * BM;

  // wait for this tile's two row-blocks to be converted
  if (tid == 0) {
    while (atomicAdd(&g_cvt_cnt[bp], 0u) < 4u ||
           atomicAdd(&g_cvt_cnt[bq], 0u) < 4u) {
      __nanosleep(64);
    }
    __threadfence();
  }
  __syncthreads();

  const __half* Ab = g_total + (size_t)rowBase * KDIM;
  const __half* Bb = g_total + (size_t)colBase * KDIM;

  uint32_t sm0 = (smem_u32(dsm) + 127u) & ~127u;

  const int warp_m = wid & 1;    // 0..1 -> 64-row half
  const int warp_n = wid >> 1;   // 0..3 -> 32-col quarter
  const int lr  = lane & 7;
  const int sub = lane >> 3;

  const uint32_t a_kbit = (uint32_t)(sub >> 1);
  const uint32_t b_kbit = (uint32_t)(sub & 1);

  uint32_t a_base[4];
  #pragma unroll
  for (int mt = 0; mt < 4; ++mt) {
    int row = warp_m * 64 + mt * 16 + (sub & 1) * 8 + lr;
    a_base[mt] = (uint32_t)row * 128u + ((a_kbit ^ (uint32_t)(row & 7)) << 4);
  }
  uint32_t b_base[2];
  #pragma unroll
  for (int np = 0; np < 2; ++np) {
    int row = warp_n * 32 + np * 16 + (sub >> 1) * 8 + lr;
    b_base[np] = (uint32_t)row * 128u + ((b_kbit ^ (uint32_t)(row & 7)) << 4);
  }

  uint32_t acc[4][4][2];   // f16x2 accumulators
  #pragma unroll
  for (int i = 0; i < 4; ++i)
    #pragma unroll
    for (int j = 0; j < 4; ++j) { acc[i][j][0] = 0u; acc[i][j][1] = 0u; }

  load_stage(sm0 + 0 * STAGE_BYTES, Ab, Bb, 0, tid);
  load_stage(sm0 + 1 * STAGE_BYTES, Ab, Bb, 1, tid);

  int st = 0;
  for (int t = 0; t < NCHUNK; ++t) {
    if (t == NCHUNK - 1) cp_wait<0>(); else cp_wait<1>();
    __syncthreads();

    uint32_t sA = sm0 + st * STAGE_BYTES;
    uint32_t sB = sA + TILE_BYTES;

    uint32_t aaddr[4], baddr[2];
    #pragma unroll
    for (int mt = 0; mt < 4; ++mt) aaddr[mt] = sA + a_base[mt];
    #pragma unroll
    for (int np = 0; np < 2; ++np) baddr[np] = sB + b_base[np];

    #pragma unroll
    for (int kk = 0; kk < 4; ++kk) {
      uint32_t af[4][4];
      #pragma unroll
      for (int mt = 0; mt < 4; ++mt) ldsm4(af[mt], aaddr[mt]);
      uint32_t bf[2][4];
      #pragma unroll
      for (int np = 0; np < 2; ++np) ldsm4(bf[np], baddr[np]);

      if (kk < 3) {
        const uint32_t x = (kk == 1) ? 0x60u : 0x20u;
        #pragma unroll
        for (int mt = 0; mt < 4; ++mt) aaddr[mt] ^= x;
        #pragma unroll
        for (int np = 0; np < 2; ++np) baddr[np] ^= x;
      }

      #pragma unroll
      for (int mt = 0; mt < 4; ++mt) {
        #pragma unroll
        for (int nt = 0; nt < 4; ++nt)
          mma16816h(acc[mt][nt], af[mt], bf[nt >> 1][(nt & 1) * 2],
                    bf[nt >> 1][(nt & 1) * 2 + 1]);
      }
    }

    __syncthreads();
    if (t + NST < NCHUNK) load_stage(sm0 + st * STAGE_BYTES, Ab, Bb, t + NST, tid);
    st ^= 1;
  }

  // ---- wait for coef (set during conversion phase; epilogues start >=30us in) ----
  if (tid == 0) {
    while (atomicAdd(&g_coef_ready, 0u) == 0u) { __nanosleep(64); }
    s_red[0] = 0.0;
  }
  __syncthreads();
  const float coef = g_coef;

  // ---- fused epilogue (exp2-based: coef already includes log2e) ----
  const int tg = lane >> 2;
  const int tc = lane & 3;

  float sqp[4][2], sqq[4][2];
  #pragma unroll
  for (int mt = 0; mt < 4; ++mt) {
    int p0 = rowBase + warp_m * 64 + mt * 16 + tg;
    sqp[mt][0] = g_sq[p0];
    sqp[mt][1] = g_sq[p0 + 8];
  }
  #pragma unroll
  for (int nt = 0; nt < 4; ++nt) {
    int q0 = colBase + warp_n * 32 + nt * 8 + tc * 2;
    sqq[nt][0] = g_sq[q0];
    sqq[nt][1] = g_sq[q0 + 1];
  }

  float fsum = 0.f;
  #pragma unroll
  for (int mt = 0; mt < 4; ++mt) {
    #pragma unroll
    for (int nt = 0; nt < 4; ++nt) {
      #pragma unroll
      for (int h = 0; h < 2; ++h) {          // h=0: row tg, h=1: row tg+8
        float2 f = __half22float2(*(const __half2*)&acc[mt][nt][h]);
        float L2a = sqp[mt][h] + sqq[nt][0] - 2.0f * f.x;
        float L2b = sqp[mt][h] + sqq[nt][1] - 2.0f * f.y;
        float va = exp2f(L2a * coef);
        float vb = exp2f(L2b * coef);
        float va2 = va * va, va4 = va2 * va2, va8 = va4 * va4;
        float vb2 = vb * vb, vb4 = vb2 * vb2, vb8 = vb4 * vb4;
        fsum += va + va2 + va4 + va8 + va8 * va8;
        fsum += vb + vb2 + vb4 + vb8 + vb8 * vb8;
      }
    }
  }
  double d = (double)fsum;
  #pragma unroll
  for (int o = 16; o; o >>= 1) d += __shfl_xor_sync(0xffffffffu, d, o);
  if (lane == 0) s_red[wid] = d;
  __syncthreads();
  if (tid == 0) {
    double t = 0.0;
    #pragma unroll
    for (int i = 0; i < 8; ++i) t += s_red[i];
    double sgn = ((bp < NTILES / 2) == (bq < NTILES / 2)) ? 1.0 : -1.0;
    if (bp != bq) sgn *= 2.0;
    atomicAdd(&g_accum, sgn * t);

    // ---- fused finalization: last CTA writes output + resets all state ----
    __threadfence();
    unsigned rank = atomicAdd(&g_donectr, 1u);
    if (rank == NBLOCKS - 1) {
      double total = atomicAdd(&g_accum, 0.0);   // ordered read after fence
      out[0] = (float)(total / ((double)NH * (double)NH));
      g_accum = 0.0;
      g_donectr = 0;
      g_coef_ready = 0;
      g_cvt_total = 0;
      #pragma unroll
      for (int i = 0; i < NTILES; ++i) g_cvt_cnt[i] = 0u;
    }
  }
}

// ---------------- host launch ----------------
extern "C" void kernel_launch(void* const* d_in, const int* in_sizes, int n_in,
                              void* d_out, int out_size) {
  (void)in_sizes; (void)n_in; (void)out_size;
  const float* S = (const float*)d_in[0];
  const float* T = (const float*)d_in[1];

  cudaFuncSetAttribute(k_gemm, cudaFuncAttributeMaxDynamicSharedMemorySize, DYN_BYTES);

  k_gemm<<<NBLOCKS, 256, DYN_BYTES>>>(S, T, (float*)d_out);
}